// round 16
// baseline (speedup 1.0000x reference)
#include <cuda_runtime.h>
#include <cuda_fp16.h>
#include <math.h>
#include <stdint.h>

// ---------------------------------------------------------------------------
// Scratch (no cudaMalloc allowed)
// ---------------------------------------------------------------------------
__device__ __half g_qkh[33554432];  // 32768 x 1024 fp16 (Q | K)
__device__ __half g_aoh[16777216];  // 32768 x 512  fp16 attention output
__device__ __half g_xh[16777216];   // 32768 x 512  fp16 x
__device__ __half g_wh[524288];     // 1024 x 512   fp16 w_qkv rows 0..1023
__device__ __half g_woh[262144];    // 512 x 512    fp16 w_out

__device__ __forceinline__ uint32_t smem_u32(const void* p) {
    uint32_t a;
    asm("{ .reg .u64 t; cvta.to.shared.u64 t, %1; cvt.u32.u64 %0, t; }"
        : "=r"(a) : "l"(p));
    return a;
}
__device__ __forceinline__ void cpa16(uint32_t s, const void* g) {
    asm volatile("cp.async.cg.shared.global [%0], [%1], 16;" :: "r"(s), "l"(g));
}
__device__ __forceinline__ void cpa16z(uint32_t s, const void* g, int sz) {
    asm volatile("cp.async.cg.shared.global [%0], [%1], 16, %2;"
                 :: "r"(s), "l"(g), "r"(sz));
}

// mma.sync m16n8k16 fp16 (fp32 accum), canonical fragment layout (LDSM-fed).
__device__ __forceinline__ void mma_f16(float* d, const uint32_t* a,
                                        const uint32_t* b) {
    asm volatile(
        "mma.sync.aligned.m16n8k16.row.col.f32.f16.f16.f32 "
        "{%0,%1,%2,%3}, {%4,%5,%6,%7}, {%8,%9}, {%0,%1,%2,%3};"
        : "+f"(d[0]), "+f"(d[1]), "+f"(d[2]), "+f"(d[3])
        : "r"(a[0]), "r"(a[1]), "r"(a[2]), "r"(a[3]), "r"(b[0]), "r"(b[1]));
}

__device__ __forceinline__ void ldsm_x4(uint32_t* r, uint32_t addr) {
    asm volatile("ldmatrix.sync.aligned.m8n8.x4.shared.b16 {%0,%1,%2,%3}, [%4];"
                 : "=r"(r[0]), "=r"(r[1]), "=r"(r[2]), "=r"(r[3]) : "r"(addr));
}
__device__ __forceinline__ void ldsm_x4t(uint32_t* r, uint32_t addr) {
    asm volatile("ldmatrix.sync.aligned.m8n8.x4.trans.shared.b16 {%0,%1,%2,%3}, [%4];"
                 : "=r"(r[0]), "=r"(r[1]), "=r"(r[2]), "=r"(r[3]) : "r"(addr));
}
__device__ __forceinline__ __half2 h2exp2a(__half2 x) {   // ex2.approx.f16x2
    uint32_t xi = *reinterpret_cast<uint32_t*>(&x), ri;
    asm("ex2.approx.f16x2 %0, %1;" : "=r"(ri) : "r"(xi));
    return *reinterpret_cast<__half2*>(&ri);
}

// ---------------------------------------------------------------------------
// fp16 mma GEMM: C[M,N] = A[M,K] @ B[N,K]^T.   (unchanged from R15)
// CTA 128x128, 256 threads = 8 warps (2x4), warp tile 64x32. LDSM fragments.
// ---------------------------------------------------------------------------
#define HSTR 72

template<bool OUT_HALF, bool BIAS>
__global__ __launch_bounds__(256, 2)
void hgemm(const __half* __restrict__ A, const __half* __restrict__ B,
           const float* __restrict__ bias, void* __restrict__ Cv,
           int N, int K)
{
    extern __shared__ __half hm[];
    __half* Abuf[2] = {hm,          hm + 9216};
    __half* Bbuf[2] = {hm + 18432,  hm + 27648};

    const int tid = threadIdx.x;
    const int wid = tid >> 5, lid = tid & 31;
    const int gid = lid >> 2, tig = lid & 3;
    const int wm = wid >> 2, wn = wid & 3;
    const int n0 = blockIdx.x * 128, m0 = blockIdx.y * 128;
    const int NC = K >> 6;

    const int aRow = (lid & 7) + ((lid >> 3) & 1) * 8;
    const int aKof = (lid >> 4) * 8;
    const int bRow = (lid & 7) + ((lid >> 4) & 1) * 8;
    const int bKof = ((lid >> 3) & 1) * 8;

    const __half* gA = A + (size_t)m0 * K;
    const __half* gB = B + (size_t)n0 * K;

    float acc[4][4][4];
#pragma unroll
    for (int mt = 0; mt < 4; mt++)
#pragma unroll
        for (int nt = 0; nt < 4; nt++)
#pragma unroll
            for (int r = 0; r < 4; r++) acc[mt][nt][r] = 0.f;

    auto load_tile = [&](__half* dst, const __half* gsrc, int c) {
#pragma unroll
        for (int l = 0; l < 4; l++) {
            int idx = tid + l * 256;
            int row = idx >> 3, q = idx & 7;
            cpa16(smem_u32(dst + row * HSTR + q * 8),
                  gsrc + (size_t)row * K + c * 64 + q * 8);
        }
    };

    load_tile(Abuf[0], gA, 0);
    load_tile(Bbuf[0], gB, 0);
    asm volatile("cp.async.commit_group;" ::: "memory");

    for (int c = 0; c < NC; c++) {
        if (c + 1 < NC) {
            int nb = (c + 1) & 1;
            load_tile(Abuf[nb], gA, c + 1);
            load_tile(Bbuf[nb], gB, c + 1);
            asm volatile("cp.async.commit_group;" ::: "memory");
            asm volatile("cp.async.wait_group 1;" ::: "memory");
        } else {
            asm volatile("cp.async.wait_group 0;" ::: "memory");
        }
        __syncthreads();

        const __half* As = Abuf[c & 1];
        const __half* Bs = Bbuf[c & 1];
#pragma unroll
        for (int s = 0; s < 4; s++) {
            const int kb = s * 16;
            uint32_t af[4][4], bf[4][2];
#pragma unroll
            for (int mt = 0; mt < 4; mt++)
                ldsm_x4(af[mt], smem_u32(As + (wm * 64 + mt * 16 + aRow) * HSTR
                                            + kb + aKof));
#pragma unroll
            for (int np = 0; np < 2; np++) {
                uint32_t r4[4];
                ldsm_x4(r4, smem_u32(Bs + (wn * 32 + np * 16 + bRow) * HSTR
                                        + kb + bKof));
                bf[np * 2 + 0][0] = r4[0]; bf[np * 2 + 0][1] = r4[1];
                bf[np * 2 + 1][0] = r4[2]; bf[np * 2 + 1][1] = r4[3];
            }
#pragma unroll
            for (int mt = 0; mt < 4; mt++)
#pragma unroll
                for (int nt = 0; nt < 4; nt++)
                    mma_f16(acc[mt][nt], af[mt], bf[nt]);
        }
        __syncthreads();
    }

#pragma unroll
    for (int mt = 0; mt < 4; mt++) {
        int row = m0 + wm * 64 + mt * 16 + gid;
#pragma unroll
        for (int nt = 0; nt < 4; nt++) {
            int col = n0 + wn * 32 + nt * 8 + 2 * tig;
            if (OUT_HALF) {
                __half* C = (__half*)Cv;
                *(__half2*)(C + (size_t)row * N + col) =
                    __floats2half2_rn(acc[mt][nt][0], acc[mt][nt][1]);
                *(__half2*)(C + (size_t)(row + 8) * N + col) =
                    __floats2half2_rn(acc[mt][nt][2], acc[mt][nt][3]);
            } else {
                float* C = (float*)Cv;
                float2 v0 = make_float2(acc[mt][nt][0], acc[mt][nt][1]);
                float2 v1 = make_float2(acc[mt][nt][2], acc[mt][nt][3]);
                if (BIAS) {
                    float2 bb = *(const float2*)(bias + col);
                    v0.x += bb.x; v0.y += bb.y;
                    v1.x += bb.x; v1.y += bb.y;
                }
                *(float2*)(C + (size_t)row * N + col) = v0;
                *(float2*)(C + (size_t)(row + 8) * N + col) = v1;
            }
        }
    }
}

// ---------------------------------------------------------------------------
// Elementwise fp32 -> fp16 conversion
// ---------------------------------------------------------------------------
__global__ void f2h_k(const float4* __restrict__ in, uint2* __restrict__ out,
                      int n4)
{
    int i = blockIdx.x * blockDim.x + threadIdx.x;
    if (i < n4) {
        float4 v = in[i];
        uint2 o;
        __half2 h0 = __floats2half2_rn(v.x, v.y);
        __half2 h1 = __floats2half2_rn(v.z, v.w);
        o.x = *reinterpret_cast<uint32_t*>(&h0);
        o.y = *reinterpret_cast<uint32_t*>(&h1);
        out[i] = o;
    }
}

// ---------------------------------------------------------------------------
// fp16 windowed attention, HALF-WINDOW CTAs: 512 CTAs (b, wi, half), 256 thr
// = 8 warps, smem 109568 B -> 2 CTAs/SM (softmax MUFU overlaps peer's MMA).
//   Phase A: S[64,256] = Q.K2^T, warp grid 2x4 (32m x 64n), LDSM frags;
//            fully-masked tile (hw==0, wn==3) skipped.
//   Softmax: REGISTER-based. Row max/sum via 4-lane shfl + 2KB stats smem.
//            exp via ex2.approx.f16x2 (2 exps / MUFU op). P -> fp16 buffer.
//   Phase C: O[64,512] = P.K2; A via ldmatrix.x4 from P; B via
//            ldmatrix.x4.trans from natural [j][d] Kc tiles; 8 chunks of 64d,
//            warp grid 4m x 2d. Chunk 0 prefetched before softmax.
// smem (bytes): P 64*264*2=33792 | Kc 2*256*72*2=73728 (at 33792) |
//               stats 2KB (at 107520). Phase-A staging (92160) overlays.
// ---------------------------------------------------------------------------
#define ASTRH 72
#define PSTRH 264
#define CSTRH 72

__global__ __launch_bounds__(256, 2)
void attn_mma(const __half* __restrict__ qk, __half* __restrict__ ao)
{
    extern __shared__ float sm[];
    __half* hmem = (__half*)sm;
    __half* Ph = hmem;                       // 64 x 264 halves
    __half* Kc = hmem + 16896;               // 2 x (256 x 72) halves
    float*  statsF = sm + 26880;             // 512 floats (max | sum)
    __half* Qb[2] = {hmem,          hmem + 4608};
    __half* Kb[2] = {hmem + 9216,   hmem + 27648};

    const int tid = threadIdx.x;
    const int wid = tid >> 5, lid = tid & 31;
    const int gid = lid >> 2, tig = lid & 3;
    const int hw = blockIdx.x & 1;
    const int wi = (blockIdx.x >> 1) & 63;
    const int b  = blockIdx.x >> 7;
    const size_t qrow0 = (size_t)b * 8192 + (size_t)wi * 128;  // window base
    const size_t qrowQ = qrow0 + hw * 64;                      // this half's Q
    const bool w0 = (wi == 0);

    // LDSM per-lane offsets
    const int aRow = (lid & 7) + ((lid >> 3) & 1) * 8;
    const int aKof = (lid >> 4) * 8;
    const int bRow = (lid & 7) + ((lid >> 4) & 1) * 8;
    const int bKof = ((lid >> 3) & 1) * 8;
    const int xRow = (lid & 7) + ((lid >> 3) & 1) * 8;   // x4.trans k-row
    const int xCol = ((lid >> 4) & 1) * 8;               // x4.trans n-block

    // ---- Phase A: S = Q . K2^T ----
    const int wm = wid >> 2, wn = wid & 3;   // 2x4 warp grid, 32m x 64n
    const bool skipA = (hw == 0) && (wn == 3);   // tile fully masked
    float acc[2][8][4];
#pragma unroll
    for (int mt = 0; mt < 2; mt++)
#pragma unroll
        for (int nt = 0; nt < 8; nt++)
#pragma unroll
            for (int r = 0; r < 4; r++) acc[mt][nt][r] = 0.f;

    const __half* Qg = qk + qrowQ * 1024;

    auto stage = [&](int c, int bi) {
        __half* sQ = Qb[bi];
        __half* sK = Kb[bi];
#pragma unroll
        for (int l = 0; l < 2; l++) {
            int idx = tid + l * 256;        // 0..511: 64 rows x 8 x 16B
            int row = idx >> 3, q = idx & 7;
            cpa16(smem_u32(sQ + row * ASTRH + q * 8),
                  Qg + (size_t)row * 1024 + c * 64 + q * 8);
        }
#pragma unroll
        for (int l = 0; l < 8; l++) {
            int idx = tid + l * 256;        // 0..2047: 256 rows x 8 x 16B
            int row = idx >> 3, q = idx & 7;
            const __half* src = qk + (qrow0 + row - 128) * 1024 + 512 + c * 64 + q * 8;
            int sz = (w0 && row < 128) ? 0 : 16;
            cpa16z(smem_u32(sK + row * ASTRH + q * 8), (w0 && row < 128) ? qk : src, sz);
        }
    };

    auto stageC = [&](int c, int bi) {
        __half* dst = Kc + bi * 18432;
#pragma unroll
        for (int l = 0; l < 8; l++) {
            int idx = tid + l * 256;        // 0..2047: 256 rows x 8 x 16B
            int row = idx >> 3, q = idx & 7;
            const __half* src = qk + (qrow0 + row - 128) * 1024 + 512 + c * 64 + q * 8;
            int sz = (w0 && row < 128) ? 0 : 16;
            cpa16z(smem_u32(dst + row * CSTRH + q * 8), (w0 && row < 128) ? qk : src, sz);
        }
    };

    stage(0, 0);
    asm volatile("cp.async.commit_group;" ::: "memory");

    for (int c = 0; c < 8; c++) {
        if (c + 1 < 8) {
            stage(c + 1, (c + 1) & 1);
            asm volatile("cp.async.commit_group;" ::: "memory");
            asm volatile("cp.async.wait_group 1;" ::: "memory");
        } else {
            asm volatile("cp.async.wait_group 0;" ::: "memory");
        }
        __syncthreads();

        if (!skipA) {
            const __half* sQ = Qb[c & 1];
            const __half* sK = Kb[c & 1];
#pragma unroll
            for (int s = 0; s < 4; s++) {
                const int kb = s * 16;
                uint32_t af[2][4], bf[8][2];
#pragma unroll
                for (int mt = 0; mt < 2; mt++)
                    ldsm_x4(af[mt], smem_u32(sQ + (wm * 32 + mt * 16 + aRow) * ASTRH
                                                + kb + aKof));
#pragma unroll
                for (int np = 0; np < 4; np++) {
                    uint32_t r4[4];
                    ldsm_x4(r4, smem_u32(sK + (wn * 64 + np * 16 + bRow) * ASTRH
                                            + kb + bKof));
                    bf[np * 2 + 0][0] = r4[0]; bf[np * 2 + 0][1] = r4[1];
                    bf[np * 2 + 1][0] = r4[2]; bf[np * 2 + 1][1] = r4[3];
                }
#pragma unroll
                for (int mt = 0; mt < 2; mt++)
#pragma unroll
                    for (int nt = 0; nt < 8; nt++)
                        mma_f16(acc[mt][nt], af[mt], bf[nt]);
            }
        }
        __syncthreads();
    }

    // Prefetch phase-C chunk 0 (overlaps softmax; Kc disjoint from P/stats).
    stageC(0, 0);
    asm volatile("cp.async.commit_group;" ::: "memory");

    // ---- register softmax ----
    {
        const float scale = 0.04419417382415922f;   // 512^-0.5
        const float L2E = 1.4426950408889634f;
        // pass 1: scale + mask + row max (4-lane shfl), partials to smem
#pragma unroll
        for (int mt = 0; mt < 2; mt++)
#pragma unroll
            for (int rh = 0; rh < 2; rh++) {
                int i_loc = wm * 32 + mt * 16 + gid + 8 * rh;
                int i_g = hw * 64 + i_loc;
                float mx = -3.402823466e38f;
#pragma unroll
                for (int nt = 0; nt < 8; nt++)
#pragma unroll
                    for (int c2 = 0; c2 < 2; c2++) {
                        int j = wn * 64 + nt * 8 + 2 * tig + c2;
                        float v = acc[mt][nt][2 * rh + c2] * scale;
                        if (j > i_g + 128) v = -3.402823466e38f;
                        acc[mt][nt][2 * rh + c2] = v;
                        mx = fmaxf(mx, v);
                    }
                mx = fmaxf(mx, __shfl_xor_sync(0xffffffffu, mx, 1));
                mx = fmaxf(mx, __shfl_xor_sync(0xffffffffu, mx, 2));
                if (tig == 0) statsF[i_loc * 4 + wn] = mx;
            }
        __syncthreads();
        // pass 2: exp (f16x2) + row sum
#pragma unroll
        for (int mt = 0; mt < 2; mt++)
#pragma unroll
            for (int rh = 0; rh < 2; rh++) {
                int i_loc = wm * 32 + mt * 16 + gid + 8 * rh;
                float4 m4 = *(const float4*)(statsF + i_loc * 4);
                float gmax = fmaxf(fmaxf(m4.x, m4.y), fmaxf(m4.z, m4.w));
                float sum = 0.f;
#pragma unroll
                for (int nt = 0; nt < 8; nt++) {
                    float d0 = (acc[mt][nt][2 * rh + 0] - gmax) * L2E;
                    float d1 = (acc[mt][nt][2 * rh + 1] - gmax) * L2E;
                    __half2 p = h2exp2a(__floats2half2_rn(d0, d1));
                    float2 pf = __half22float2(p);
                    sum += pf.x + pf.y;
                    acc[mt][nt][2 * rh] = __uint_as_float(
                        *reinterpret_cast<uint32_t*>(&p));   // stash bits
                }
                sum += __shfl_xor_sync(0xffffffffu, sum, 1);
                sum += __shfl_xor_sync(0xffffffffu, sum, 2);
                if (tig == 0) statsF[256 + i_loc * 4 + wn] = sum;
            }
        __syncthreads();
        // pass 3: normalize + store P fp16
#pragma unroll
        for (int mt = 0; mt < 2; mt++)
#pragma unroll
            for (int rh = 0; rh < 2; rh++) {
                int i_loc = wm * 32 + mt * 16 + gid + 8 * rh;
                float4 s4 = *(const float4*)(statsF + 256 + i_loc * 4);
                float inv = 1.f / (s4.x + s4.y + s4.z + s4.w);
                __half2 hinv = __half2half2(__float2half_rn(inv));
#pragma unroll
                for (int nt = 0; nt < 8; nt++) {
                    uint32_t pb = __float_as_uint(acc[mt][nt][2 * rh]);
                    __half2 p = __hmul2(*reinterpret_cast<__half2*>(&pb), hinv);
                    *(__half2*)(Ph + i_loc * PSTRH + wn * 64 + nt * 8 + 2 * tig) = p;
                }
            }
    }
    __syncthreads();

    // ---- Phase C: O = P . K2, 8 chunks of 64 d; warp grid 4m x 2d ----
    const int wm2 = wid >> 1, wn2 = wid & 1;   // 16m x 32d warp tiles
    for (int co = 0; co < 8; co++) {
        if (co + 1 < 8) {
            stageC(co + 1, (co + 1) & 1);
            asm volatile("cp.async.commit_group;" ::: "memory");
            asm volatile("cp.async.wait_group 1;" ::: "memory");
        } else {
            asm volatile("cp.async.wait_group 0;" ::: "memory");
        }
        __syncthreads();

        const __half* Kcb = Kc + (co & 1) * 18432;
        float a2[4][4];
#pragma unroll
        for (int nt = 0; nt < 4; nt++)
#pragma unroll
            for (int r = 0; r < 4; r++) a2[nt][r] = 0.f;

#pragma unroll 4
        for (int k16 = 0; k16 < 16; k16++) {
            const int kb = k16 * 16;
            uint32_t af[4], bf[4][2];
            ldsm_x4(af, smem_u32(Ph + (wm2 * 16 + aRow) * PSTRH + kb + aKof));
#pragma unroll
            for (int nb = 0; nb < 2; nb++) {
                uint32_t r4[4];
                ldsm_x4t(r4, smem_u32(Kcb + (kb + xRow) * CSTRH
                                          + wn2 * 32 + nb * 16 + xCol));
                bf[nb * 2 + 0][0] = r4[0]; bf[nb * 2 + 0][1] = r4[1];
                bf[nb * 2 + 1][0] = r4[2]; bf[nb * 2 + 1][1] = r4[3];
            }
#pragma unroll
            for (int nt = 0; nt < 4; nt++)
                mma_f16(a2[nt], af, bf[nt]);
        }

        int c0 = co * 64;
        size_t row = qrowQ + wm2 * 16 + gid;
#pragma unroll
        for (int nt = 0; nt < 4; nt++) {
            int col = c0 + wn2 * 32 + nt * 8 + 2 * tig;
            *(__half2*)(ao + row * 512 + col) =
                __floats2half2_rn(a2[nt][0], a2[nt][1]);
            *(__half2*)(ao + (row + 8) * 512 + col) =
                __floats2half2_rn(a2[nt][2], a2[nt][3]);
        }
        __syncthreads();
    }
}

// ---------------------------------------------------------------------------
extern "C" void kernel_launch(void* const* d_in, const int* in_sizes, int n_in,
                              void* d_out, int out_size)
{
    (void)in_sizes; (void)n_in; (void)out_size;
    const float* x     = (const float*)d_in[0];   // (4,8192,512)
    const float* w_qkv = (const float*)d_in[1];   // (1536,512); rows 0..1023 used
    const float* w_out = (const float*)d_in[2];   // (512,512)
    const float* b_out = (const float*)d_in[3];   // (512,)
    float* out = (float*)d_out;                   // (4,8192,512)

    __half *qkh, *aoh, *xh, *wh, *woh;
    cudaGetSymbolAddress((void**)&qkh, g_qkh);
    cudaGetSymbolAddress((void**)&aoh, g_aoh);
    cudaGetSymbolAddress((void**)&xh,  g_xh);
    cudaGetSymbolAddress((void**)&wh,  g_wh);
    cudaGetSymbolAddress((void**)&woh, g_woh);

    cudaFuncSetAttribute(attn_mma,
                         cudaFuncAttributeMaxDynamicSharedMemorySize, 109568);
    cudaFuncSetAttribute((const void*)hgemm<true, false>,
                         cudaFuncAttributeMaxDynamicSharedMemorySize, 73728);
    cudaFuncSetAttribute((const void*)hgemm<false, true>,
                         cudaFuncAttributeMaxDynamicSharedMemorySize, 73728);

    // 0) Convert operands to fp16.
    f2h_k<<<(4194304 + 255) / 256, 256>>>((const float4*)x, (uint2*)xh, 4194304);
    f2h_k<<<(131072  + 255) / 256, 256>>>((const float4*)w_qkv, (uint2*)wh, 131072);
    f2h_k<<<(65536   + 255) / 256, 256>>>((const float4*)w_out, (uint2*)woh, 65536);

    // 1) QK projection (fp16 in, fp16 out). V is dead in the reference.
    {
        dim3 g(1024 / 128, 32768 / 128);
        hgemm<true, false><<<g, 256, 73728>>>(xh, wh, nullptr, qkh, 1024, 512);
    }

    // 2) fp16 windowed attention: 512 half-window CTAs, 2 CTAs/SM.
    attn_mma<<<512, 256, 109568>>>(qkh, aoh);

    // 3) Output projection + bias (fp16 in, fp32 out).
    {
        dim3 g(512 / 128, 32768 / 128);
        hgemm<false, true><<<g, 256, 73728>>>(aoh, woh, b_out, out, 512, 512);
    }
}